// round 1
// baseline (speedup 1.0000x reference)
#include <cuda_runtime.h>
#include <math.h>

// Problem constants
static const int B_ = 4;
static const int T_ = 1024;
static const int E_ = 2048;
static const int H_ = 32;
static const int D_ = 64;
static const int BT_ = B_ * T_;      // 4096
static const int BH_ = B_ * H_;      // 128

// Scratch (device globals; no allocation allowed)
__device__ float g_q[BH_ * T_ * D_];   // [B,H,T,D]
__device__ float g_k[BH_ * T_ * D_];
__device__ float g_v[BH_ * T_ * D_];
__device__ float g_s[BH_ * D_];        // SmoothK per-channel scale
__device__ float g_ctx[BT_ * E_];      // attention output [B,T,E]

// ---------------------------------------------------------------------------
// SGEMM: C = A @ W^T + bias, optionally scaled. A [M,K] row-major,
// W [N,K] row-major (so both operands are K-contiguous: "NT" dot-product GEMM).
// MODE 0: write C row-major [M,N].
// MODE 1: write split-head transposed: m=(b,t), n=(h,d) -> out[b,h,t,d].
// 128x128x16 tiles, 256 threads, 8x8 per-thread fragments.
// ---------------------------------------------------------------------------
template <int MODE>
__global__ __launch_bounds__(256) void sgemm_nt(
    const float* __restrict__ A, const float* __restrict__ W,
    const float* __restrict__ bias, float* __restrict__ C,
    int M, int N, int K, float scale)
{
    __shared__ float As[16][128];
    __shared__ float Bs[16][128];

    const int bm = blockIdx.y * 128;
    const int bn = blockIdx.x * 128;
    const int tid = threadIdx.x;
    const int tx = tid & 15;
    const int ty = tid >> 4;

    // global load mapping: 2 rows x 1 float4 per thread per operand
    const int lr = tid >> 2;          // 0..63
    const int lc = (tid & 3) * 4;     // 0,4,8,12

    const float* Ap = A + (size_t)(bm + lr) * K + lc;
    const float* Wp = W + (size_t)(bn + lr) * K + lc;

    float acc[8][8];
#pragma unroll
    for (int i = 0; i < 8; i++)
#pragma unroll
        for (int j = 0; j < 8; j++) acc[i][j] = 0.f;

    for (int k0 = 0; k0 < K; k0 += 16) {
        float4 a0 = *(const float4*)(Ap + k0);
        float4 a1 = *(const float4*)(Ap + (size_t)64 * K + k0);
        float4 b0 = *(const float4*)(Wp + k0);
        float4 b1 = *(const float4*)(Wp + (size_t)64 * K + k0);

        __syncthreads();
        As[lc + 0][lr] = a0.x; As[lc + 1][lr] = a0.y;
        As[lc + 2][lr] = a0.z; As[lc + 3][lr] = a0.w;
        As[lc + 0][lr + 64] = a1.x; As[lc + 1][lr + 64] = a1.y;
        As[lc + 2][lr + 64] = a1.z; As[lc + 3][lr + 64] = a1.w;
        Bs[lc + 0][lr] = b0.x; Bs[lc + 1][lr] = b0.y;
        Bs[lc + 2][lr] = b0.z; Bs[lc + 3][lr] = b0.w;
        Bs[lc + 0][lr + 64] = b1.x; Bs[lc + 1][lr + 64] = b1.y;
        Bs[lc + 2][lr + 64] = b1.z; Bs[lc + 3][lr + 64] = b1.w;
        __syncthreads();

#pragma unroll
        for (int kk = 0; kk < 16; kk++) {
            float a[8], b[8];
            *(float4*)(a)     = *(const float4*)(&As[kk][ty * 8]);
            *(float4*)(a + 4) = *(const float4*)(&As[kk][ty * 8 + 4]);
            *(float4*)(b)     = *(const float4*)(&Bs[kk][tx * 8]);
            *(float4*)(b + 4) = *(const float4*)(&Bs[kk][tx * 8 + 4]);
#pragma unroll
            for (int i = 0; i < 8; i++)
#pragma unroll
                for (int j = 0; j < 8; j++)
                    acc[i][j] += a[i] * b[j];
        }
    }

#pragma unroll
    for (int i = 0; i < 8; i++) {
        const int m = bm + ty * 8 + i;
#pragma unroll
        for (int j = 0; j < 8; j++) {
            const int n = bn + tx * 8 + j;
            float v = (acc[i][j] + bias[n]) * scale;
            if (MODE == 0) {
                C[(size_t)m * N + n] = v;
            } else {
                const int b = m >> 10, t = m & 1023;
                const int h = n >> 6, d = n & 63;
                C[(((size_t)(b * H_ + h)) * T_ + t) * D_ + d] = v;
            }
        }
    }
}

// ---------------------------------------------------------------------------
// SmoothK per-channel abs-max over tokens: s[b,h,d] = clip(max_t |K|, 1e-5)
// ---------------------------------------------------------------------------
__global__ __launch_bounds__(256) void smooth_absmax(
    const float* __restrict__ Kin, float* __restrict__ S)
{
    const int bh = blockIdx.x;
    const int dt = threadIdx.x >> 6;
    const int d = threadIdx.x & 63;
    const float* p = Kin + (size_t)bh * T_ * D_ + d;
    float m = 0.f;
    for (int t = dt; t < T_; t += 4) m = fmaxf(m, fabsf(p[(size_t)t * D_]));
    __shared__ float sm[4][64];
    sm[dt][d] = m;
    __syncthreads();
    if (dt == 0) {
        float r = fmaxf(fmaxf(sm[0][d], sm[1][d]), fmaxf(sm[2][d], sm[3][d]));
        S[bh * 64 + d] = fmaxf(r, 1e-5f);
    }
}

// ---------------------------------------------------------------------------
// Per-row (over last dim, D=64) asymmetric fake quant. One warp per row,
// 2 elements per lane. SMOOTH: divide by s before quant, multiply back after.
// ---------------------------------------------------------------------------
template <bool SMOOTH>
__global__ __launch_bounds__(256) void row_quant(
    float* __restrict__ X, const float* __restrict__ S)
{
    const int row = blockIdx.x * 8 + (threadIdx.x >> 5);
    const int lane = threadIdx.x & 31;
    float* p = X + (size_t)row * 64;

    float s0 = 1.f, s1 = 1.f;
    if (SMOOTH) {
        const int bh = row >> 10;
        s0 = S[bh * 64 + lane];
        s1 = S[bh * 64 + lane + 32];
    }
    float x0 = p[lane] / s0;
    float x1 = p[lane + 32] / s1;

    float mx = fmaxf(fmaxf(x0, x1), 0.f);
    float mn = fminf(fminf(x0, x1), 0.f);
#pragma unroll
    for (int o = 16; o > 0; o >>= 1) {
        mx = fmaxf(mx, __shfl_xor_sync(0xffffffffu, mx, o));
        mn = fminf(mn, __shfl_xor_sync(0xffffffffu, mn, o));
    }
    float scale = (mx - mn) / 255.0f;
    if (scale <= 0.f) scale = 1.f;
    const float zero = rintf(-mn / scale);
    float q0 = fminf(fmaxf(rintf(x0 / scale) + zero, 0.f), 255.f);
    float q1 = fminf(fmaxf(rintf(x1 / scale) + zero, 0.f), 255.f);
    p[lane]      = scale * (q0 - zero) * s0;
    p[lane + 32] = scale * (q1 - zero) * s1;
}

// ---------------------------------------------------------------------------
// V fake quant along the token axis: per (b,h,d) reduce over t, then quantize.
// Block per (b,h); thread = (dt in 0..3, d in 0..63). Two passes, coalesced.
// ---------------------------------------------------------------------------
__global__ __launch_bounds__(256) void v_quant(float* __restrict__ V)
{
    const int bh = blockIdx.x;
    const int dt = threadIdx.x >> 6;
    const int d = threadIdx.x & 63;
    float* p = V + (size_t)bh * T_ * D_ + d;

    float mx = 0.f, mn = 0.f;
    for (int t = dt; t < T_; t += 4) {
        float x = p[(size_t)t * D_];
        mx = fmaxf(mx, x);
        mn = fminf(mn, x);
    }
    __shared__ float smx[4][64], smn[4][64];
    smx[dt][d] = mx; smn[dt][d] = mn;
    __syncthreads();
    mx = fmaxf(fmaxf(smx[0][d], smx[1][d]), fmaxf(smx[2][d], smx[3][d]));
    mn = fminf(fminf(smn[0][d], smn[1][d]), fminf(smn[2][d], smn[3][d]));

    float scale = (mx - mn) / 255.0f;
    if (scale <= 0.f) scale = 1.f;
    const float zero = rintf(-mn / scale);
    for (int t = dt; t < T_; t += 4) {
        float x = p[(size_t)t * D_];
        float q = fminf(fmaxf(rintf(x / scale) + zero, 0.f), 255.f);
        p[(size_t)t * D_] = scale * (q - zero);
    }
}

// ---------------------------------------------------------------------------
// Fused causal attention (flash-style, fp32). Block = (qtile of 64, bh).
// 256 threads as 16x16; fragments 4x4. P is written into the K smem tile.
// m/l kept in registers, replicated across the 16 lanes that share each row.
// ---------------------------------------------------------------------------
static const int AP_ = 68;  // padded smem row stride (floats)

__global__ __launch_bounds__(256) void attn_fwd(
    const float* __restrict__ Q, const float* __restrict__ Kb,
    const float* __restrict__ Vb, float* __restrict__ ctx)
{
    extern __shared__ float sm[];
    float* Qs = sm;                 // [64][AP]
    float* Ks = sm + 64 * AP_;      // [64][AP], reused for P
    float* Vs = sm + 2 * 64 * AP_;  // [64][AP]

    const int bh = blockIdx.y;
    const int qt = blockIdx.x;
    const int q0 = qt * 64;
    const int tid = threadIdx.x;
    const int tx = tid & 15;
    const int ty = tid >> 4;
    const size_t base = (size_t)bh * T_ * D_;

    // load Q tile (coalesced; conflict-free padded stores)
#pragma unroll
    for (int it = 0; it < 16; it++) {
        int idx = it * 256 + tid;
        int r = idx >> 6, c = idx & 63;
        Qs[r * AP_ + c] = Q[base + (size_t)(q0 + r) * D_ + c];
    }

    float m_i[4], l_i[4], o[4][4];
#pragma unroll
    for (int i = 0; i < 4; i++) {
        m_i[i] = -1e30f;
        l_i[i] = 0.f;
#pragma unroll
        for (int x = 0; x < 4; x++) o[i][x] = 0.f;
    }

    for (int kt = 0; kt <= qt; kt++) {
        const int k0 = kt * 64;
        __syncthreads();  // prior GEMM2 reads of Ks(P)/Vs done
#pragma unroll
        for (int it = 0; it < 16; it++) {
            int idx = it * 256 + tid;
            int r = idx >> 6, c = idx & 63;
            Ks[r * AP_ + c] = Kb[base + (size_t)(k0 + r) * D_ + c];
            Vs[r * AP_ + c] = Vb[base + (size_t)(k0 + r) * D_ + c];
        }
        __syncthreads();

        // GEMM1: S = Q @ K^T, fragment rows ty+16i, cols tx+16j
        float s_acc[4][4];
#pragma unroll
        for (int i = 0; i < 4; i++)
#pragma unroll
            for (int j = 0; j < 4; j++) s_acc[i][j] = 0.f;

#pragma unroll 16
        for (int dd = 0; dd < 64; dd++) {
            float a[4], b[4];
#pragma unroll
            for (int i = 0; i < 4; i++) a[i] = Qs[(ty + 16 * i) * AP_ + dd];
#pragma unroll
            for (int j = 0; j < 4; j++) b[j] = Ks[(tx + 16 * j) * AP_ + dd];
#pragma unroll
            for (int i = 0; i < 4; i++)
#pragma unroll
                for (int j = 0; j < 4; j++) s_acc[i][j] += a[i] * b[j];
        }

        // causal mask on the diagonal tile
        if (kt == qt) {
#pragma unroll
            for (int i = 0; i < 4; i++)
#pragma unroll
                for (int j = 0; j < 4; j++)
                    if (tx + 16 * j > ty + 16 * i) s_acc[i][j] = -INFINITY;
        }

        // online softmax (per-row state replicated across 16 lanes)
        float alpha[4];
#pragma unroll
        for (int i = 0; i < 4; i++) {
            float rm = fmaxf(fmaxf(s_acc[i][0], s_acc[i][1]),
                             fmaxf(s_acc[i][2], s_acc[i][3]));
#pragma unroll
            for (int off = 8; off > 0; off >>= 1)
                rm = fmaxf(rm, __shfl_xor_sync(0xffffffffu, rm, off));
            float mnew = fmaxf(m_i[i], rm);
            alpha[i] = __expf(m_i[i] - mnew);
            float rs = 0.f;
#pragma unroll
            for (int j = 0; j < 4; j++) {
                float pvi = __expf(s_acc[i][j] - mnew);
                s_acc[i][j] = pvi;
                rs += pvi;
            }
#pragma unroll
            for (int off = 8; off > 0; off >>= 1)
                rs += __shfl_xor_sync(0xffffffffu, rs, off);
            l_i[i] = l_i[i] * alpha[i] + rs;
            m_i[i] = mnew;
#pragma unroll
            for (int x = 0; x < 4; x++) o[i][x] *= alpha[i];
        }

        // write P into the K tile (after all GEMM1 reads complete)
        __syncthreads();
#pragma unroll
        for (int i = 0; i < 4; i++)
#pragma unroll
            for (int j = 0; j < 4; j++)
                Ks[(ty + 16 * i) * AP_ + (tx + 16 * j)] = s_acc[i][j];
        __syncthreads();

        // GEMM2: O += P @ V, fragment rows ty+16i, cols tx*4+x
#pragma unroll 16
        for (int j0 = 0; j0 < 64; j0++) {
            const float4 bv = *(const float4*)(&Vs[j0 * AP_ + (tx << 2)]);
#pragma unroll
            for (int i = 0; i < 4; i++) {
                float a = Ks[(ty + 16 * i) * AP_ + j0];
                o[i][0] += a * bv.x;
                o[i][1] += a * bv.y;
                o[i][2] += a * bv.z;
                o[i][3] += a * bv.w;
            }
        }
    }

    // epilogue: normalize and write ctx[b, t, h*64+d]
    const int b = bh >> 5;
    const int h = bh & 31;
#pragma unroll
    for (int i = 0; i < 4; i++) {
        const float inv = 1.0f / l_i[i];
        const int q = q0 + ty + 16 * i;
        float4 v;
        v.x = o[i][0] * inv; v.y = o[i][1] * inv;
        v.z = o[i][2] * inv; v.w = o[i][3] * inv;
        *(float4*)(&ctx[((size_t)(b * T_ + q)) * E_ + h * 64 + (tx << 2)]) = v;
    }
}

// ---------------------------------------------------------------------------
extern "C" void kernel_launch(void* const* d_in, const int* in_sizes, int n_in,
                              void* d_out, int out_size)
{
    (void)in_sizes; (void)n_in; (void)out_size;
    const float* hs = (const float*)d_in[0];
    const float* wq = (const float*)d_in[1];
    const float* bq = (const float*)d_in[2];
    const float* wk = (const float*)d_in[3];
    const float* bk = (const float*)d_in[4];
    const float* wv = (const float*)d_in[5];
    const float* bv = (const float*)d_in[6];
    const float* wo = (const float*)d_in[7];
    const float* bo = (const float*)d_in[8];
    float* out = (float*)d_out;

    float *q, *k, *v, *s, *ctx;
    cudaGetSymbolAddress((void**)&q, g_q);
    cudaGetSymbolAddress((void**)&k, g_k);
    cudaGetSymbolAddress((void**)&v, g_v);
    cudaGetSymbolAddress((void**)&s, g_s);
    cudaGetSymbolAddress((void**)&ctx, g_ctx);

    const int smem_attn = 3 * 64 * AP_ * (int)sizeof(float);  // 52224
    cudaFuncSetAttribute(attn_fwd, cudaFuncAttributeMaxDynamicSharedMemorySize,
                         smem_attn);

    dim3 gemmGrid(E_ / 128, BT_ / 128);  // (16, 32)

    // QKV projections (Q gets the d^-0.5 scaling folded into the epilogue)
    sgemm_nt<1><<<gemmGrid, 256>>>(hs, wq, bq, q, BT_, E_, E_, 0.125f);
    sgemm_nt<1><<<gemmGrid, 256>>>(hs, wk, bk, k, BT_, E_, E_, 1.0f);
    sgemm_nt<1><<<gemmGrid, 256>>>(hs, wv, bv, v, BT_, E_, E_, 1.0f);

    // SmoothK scale + fake quant K / Q / V
    smooth_absmax<<<BH_, 256>>>(k, s);
    row_quant<true><<<BH_ * T_ / 8, 256>>>(k, s);
    row_quant<false><<<BH_ * T_ / 8, 256>>>(q, nullptr);
    v_quant<<<BH_, 256>>>(v);

    // fused causal attention
    attn_fwd<<<dim3(T_ / 64, BH_), 256, smem_attn>>>(q, k, v, ctx);

    // output projection
    sgemm_nt<0><<<gemmGrid, 256>>>(ctx, wo, bo, out, BT_, E_, E_, 1.0f);
}

// round 3
// speedup vs baseline: 1.3194x; 1.3194x over previous
#include <cuda_runtime.h>
#include <math.h>
#include <stdint.h>

// Problem constants
static const int B_ = 4;
static const int T_ = 1024;
static const int E_ = 2048;
static const int H_ = 32;
static const int D_ = 64;
static const int BT_ = B_ * T_;      // 4096
static const int BH_ = B_ * H_;      // 128

// Scratch (device globals; no allocation allowed)
__device__ float g_q[BH_ * T_ * D_];   // [B,H,T,D]
__device__ float g_k[BH_ * T_ * D_];
__device__ float g_v[BH_ * T_ * D_];
__device__ float g_s[BH_ * D_];        // SmoothK per-channel scale
__device__ float g_ctx[BT_ * E_];      // attention output [B,T,E]

// ============================================================================
// 3xTF32 GEMM via Ampere-style mma.sync (baseline PTX, compiles on compute_103)
// C = (A @ W^T + bias) * scale.  A [M,2048] fp32 row-major, W [N,2048] fp32
// row-major. The fp32 -> (tf32 hi, tf32 lo) split is fused into the smem fill.
// CTA tile 128x128, K-chunk 32, 8 warps as 2(m) x 4(n), warp tile 64x32.
// MODE 0: C row-major [M,2048]. MODE 1: split-head out[b,h,t,d].
// ============================================================================
static const int GK_ = 2048;
static const int NCH_ = GK_ / 32;        // 64 chunks
static const int LDSW_ = 36;             // padded smem row stride (floats)
static const int TILE_F_ = 128 * LDSW_;  // 4608 floats per tile
static const int GEMM_SMEM_ = 4 * TILE_F_ * 4;  // AH, AL, BH, BL = 73728 B

__device__ __forceinline__ uint32_t tf32_hi(float x) {
    uint32_t h;
    asm("cvt.rna.tf32.f32 %0, %1;" : "=r"(h) : "f"(x));
    return h;
}
__device__ __forceinline__ void tf32_split(float x, uint32_t& h, uint32_t& l) {
    h = tf32_hi(x);
    float r = x - __uint_as_float(h);
    l = tf32_hi(r);
}

__device__ __forceinline__ void mma_tf32(float* c, const uint32_t* a,
                                         const uint32_t* b) {
    asm volatile(
        "mma.sync.aligned.m16n8k8.row.col.f32.tf32.tf32.f32 "
        "{%0,%1,%2,%3}, {%4,%5,%6,%7}, {%8,%9}, {%0,%1,%2,%3};"
        : "+f"(c[0]), "+f"(c[1]), "+f"(c[2]), "+f"(c[3])
        : "r"(a[0]), "r"(a[1]), "r"(a[2]), "r"(a[3]), "r"(b[0]), "r"(b[1]));
}

template <int MODE>
__global__ __launch_bounds__(256, 1) void tc_gemm(
    const float* __restrict__ A, const float* __restrict__ W,
    const float* __restrict__ bias, float* __restrict__ C, float scale)
{
    extern __shared__ float smf[];
    float* AH = smf;
    float* AL = smf + TILE_F_;
    float* BH = smf + 2 * TILE_F_;
    float* BL = smf + 3 * TILE_F_;

    const int tid = threadIdx.x;
    const int wid = tid >> 5;
    const int lane = tid & 31;
    const int bm = blockIdx.y * 128;
    const int bn = blockIdx.x * 128;

    const int wm = (wid & 1) * 64;   // warp m offset (2 warps over m)
    const int wn = (wid >> 1) * 32;  // warp n offset (4 warps over n)
    const int gq = lane >> 2;        // group id 0..7
    const int tg = lane & 3;         // thread-in-group 0..3

    // global load geometry: float4 g = tid + 256*j; row = g/8, k4 = g%8
    int row[4], sa[4];
    size_t offA[4], offB[4];
#pragma unroll
    for (int j = 0; j < 4; j++) {
        int g = tid + 256 * j;
        row[j] = g >> 3;
        int k4 = g & 7;
        sa[j] = row[j] * LDSW_ + k4 * 4;
        offA[j] = (size_t)(bm + row[j]) * GK_ + k4 * 4;
        offB[j] = (size_t)(bn + row[j]) * GK_ + k4 * 4;
    }

    float acc[4][4][4];  // [mt][nt][4]
#pragma unroll
    for (int mt = 0; mt < 4; mt++)
#pragma unroll
        for (int nt = 0; nt < 4; nt++)
#pragma unroll
            for (int x = 0; x < 4; x++) acc[mt][nt][x] = 0.f;

    // fill chunk 0
    {
#pragma unroll
        for (int j = 0; j < 4; j++) {
            float4 va = *(const float4*)(A + offA[j]);
            float4 vb = *(const float4*)(W + offB[j]);
            uint32_t h0, h1, h2, h3, l0, l1, l2, l3;
            tf32_split(va.x, h0, l0); tf32_split(va.y, h1, l1);
            tf32_split(va.z, h2, l2); tf32_split(va.w, h3, l3);
            *(uint4*)(AH + sa[j]) = make_uint4(h0, h1, h2, h3);
            *(uint4*)(AL + sa[j]) = make_uint4(l0, l1, l2, l3);
            tf32_split(vb.x, h0, l0); tf32_split(vb.y, h1, l1);
            tf32_split(vb.z, h2, l2); tf32_split(vb.w, h3, l3);
            *(uint4*)(BH + sa[j]) = make_uint4(h0, h1, h2, h3);
            *(uint4*)(BL + sa[j]) = make_uint4(l0, l1, l2, l3);
        }
    }
    __syncthreads();

    for (int c = 0; c < NCH_; c++) {
        // prefetch chunk c+1 into registers
        float4 pa[4], pb[4];
        const bool pf = (c + 1 < NCH_);
        if (pf) {
            const int k0 = (c + 1) * 32;
#pragma unroll
            for (int j = 0; j < 4; j++) {
                pa[j] = *(const float4*)(A + offA[j] + k0);
                pb[j] = *(const float4*)(W + offB[j] + k0);
            }
        }

        // MMA phase over the 32-wide chunk (4 k-steps of 8)
#pragma unroll
        for (int ks = 0; ks < 4; ks++) {
            const int ko = ks * 8;
            uint32_t ah[4][4], al[4][4], bh[4][2], bl[4][2];
#pragma unroll
            for (int mt = 0; mt < 4; mt++) {
                const int r0 = (wm + mt * 16 + gq) * LDSW_ + ko + tg;
                ah[mt][0] = __float_as_uint(AH[r0]);
                ah[mt][1] = __float_as_uint(AH[r0 + 8 * LDSW_]);
                ah[mt][2] = __float_as_uint(AH[r0 + 4]);
                ah[mt][3] = __float_as_uint(AH[r0 + 8 * LDSW_ + 4]);
                al[mt][0] = __float_as_uint(AL[r0]);
                al[mt][1] = __float_as_uint(AL[r0 + 8 * LDSW_]);
                al[mt][2] = __float_as_uint(AL[r0 + 4]);
                al[mt][3] = __float_as_uint(AL[r0 + 8 * LDSW_ + 4]);
            }
#pragma unroll
            for (int nt = 0; nt < 4; nt++) {
                const int r0 = (wn + nt * 8 + gq) * LDSW_ + ko + tg;
                bh[nt][0] = __float_as_uint(BH[r0]);
                bh[nt][1] = __float_as_uint(BH[r0 + 4]);
                bl[nt][0] = __float_as_uint(BL[r0]);
                bl[nt][1] = __float_as_uint(BL[r0 + 4]);
            }
#pragma unroll
            for (int mt = 0; mt < 4; mt++)
#pragma unroll
                for (int nt = 0; nt < 4; nt++) {
                    mma_tf32(acc[mt][nt], ah[mt], bh[nt]);
                    mma_tf32(acc[mt][nt], al[mt], bh[nt]);
                    mma_tf32(acc[mt][nt], ah[mt], bl[nt]);
                }
        }
        __syncthreads();

        if (pf) {
#pragma unroll
            for (int j = 0; j < 4; j++) {
                uint32_t h0, h1, h2, h3, l0, l1, l2, l3;
                tf32_split(pa[j].x, h0, l0); tf32_split(pa[j].y, h1, l1);
                tf32_split(pa[j].z, h2, l2); tf32_split(pa[j].w, h3, l3);
                *(uint4*)(AH + sa[j]) = make_uint4(h0, h1, h2, h3);
                *(uint4*)(AL + sa[j]) = make_uint4(l0, l1, l2, l3);
                tf32_split(pb[j].x, h0, l0); tf32_split(pb[j].y, h1, l1);
                tf32_split(pb[j].z, h2, l2); tf32_split(pb[j].w, h3, l3);
                *(uint4*)(BH + sa[j]) = make_uint4(h0, h1, h2, h3);
                *(uint4*)(BL + sa[j]) = make_uint4(l0, l1, l2, l3);
            }
            __syncthreads();
        }
    }

    // epilogue: c frag mapping row = gq(+8), col = tg*2(+1)
#pragma unroll
    for (int mt = 0; mt < 4; mt++) {
#pragma unroll
        for (int nt = 0; nt < 4; nt++) {
            const int n0 = bn + wn + nt * 8 + tg * 2;
            const float b0 = bias[n0], b1 = bias[n0 + 1];
#pragma unroll
            for (int half = 0; half < 2; half++) {
                const int m = bm + wm + mt * 16 + gq + half * 8;
                float2 v;
                v.x = (acc[mt][nt][half * 2 + 0] + b0) * scale;
                v.y = (acc[mt][nt][half * 2 + 1] + b1) * scale;
                if (MODE == 0) {
                    *(float2*)(C + (size_t)m * E_ + n0) = v;
                } else {
                    const int b = m >> 10, t = m & 1023;
                    const int h = n0 >> 6, d0 = n0 & 63;
                    *(float2*)(C + (((size_t)(b * H_ + h)) * T_ + t) * D_ + d0) = v;
                }
            }
        }
    }
}

// ---------------------------------------------------------------------------
// SmoothK per-channel abs-max over tokens
// ---------------------------------------------------------------------------
__global__ __launch_bounds__(256) void smooth_absmax(
    const float* __restrict__ Kin, float* __restrict__ S)
{
    const int bh = blockIdx.x;
    const int dt = threadIdx.x >> 6;
    const int d = threadIdx.x & 63;
    const float* p = Kin + (size_t)bh * T_ * D_ + d;
    float m = 0.f;
    for (int t = dt; t < T_; t += 4) m = fmaxf(m, fabsf(p[(size_t)t * D_]));
    __shared__ float sm[4][64];
    sm[dt][d] = m;
    __syncthreads();
    if (dt == 0) {
        float r = fmaxf(fmaxf(sm[0][d], sm[1][d]), fmaxf(sm[2][d], sm[3][d]));
        S[bh * 64 + d] = fmaxf(r, 1e-5f);
    }
}

// ---------------------------------------------------------------------------
// Per-row (over D=64) asymmetric fake quant
// ---------------------------------------------------------------------------
template <bool SMOOTH>
__global__ __launch_bounds__(256) void row_quant(
    float* __restrict__ X, const float* __restrict__ S)
{
    const int row = blockIdx.x * 8 + (threadIdx.x >> 5);
    const int lane = threadIdx.x & 31;
    float* p = X + (size_t)row * 64;

    float s0 = 1.f, s1 = 1.f;
    if (SMOOTH) {
        const int bh = row >> 10;
        s0 = S[bh * 64 + lane];
        s1 = S[bh * 64 + lane + 32];
    }
    float x0 = p[lane] / s0;
    float x1 = p[lane + 32] / s1;

    float mx = fmaxf(fmaxf(x0, x1), 0.f);
    float mn = fminf(fminf(x0, x1), 0.f);
#pragma unroll
    for (int o = 16; o > 0; o >>= 1) {
        mx = fmaxf(mx, __shfl_xor_sync(0xffffffffu, mx, o));
        mn = fminf(mn, __shfl_xor_sync(0xffffffffu, mn, o));
    }
    float scale = (mx - mn) / 255.0f;
    if (scale <= 0.f) scale = 1.f;
    const float zero = rintf(-mn / scale);
    float q0 = fminf(fmaxf(rintf(x0 / scale) + zero, 0.f), 255.f);
    float q1 = fminf(fmaxf(rintf(x1 / scale) + zero, 0.f), 255.f);
    p[lane]      = scale * (q0 - zero) * s0;
    p[lane + 32] = scale * (q1 - zero) * s1;
}

// ---------------------------------------------------------------------------
// V fake quant along the token axis
// ---------------------------------------------------------------------------
__global__ __launch_bounds__(256) void v_quant(float* __restrict__ V)
{
    const int bh = blockIdx.x;
    const int dt = threadIdx.x >> 6;
    const int d = threadIdx.x & 63;
    float* p = V + (size_t)bh * T_ * D_ + d;

    float mx = 0.f, mn = 0.f;
    for (int t = dt; t < T_; t += 4) {
        float x = p[(size_t)t * D_];
        mx = fmaxf(mx, x);
        mn = fminf(mn, x);
    }
    __shared__ float smx[4][64], smn[4][64];
    smx[dt][d] = mx; smn[dt][d] = mn;
    __syncthreads();
    mx = fmaxf(fmaxf(smx[0][d], smx[1][d]), fmaxf(smx[2][d], smx[3][d]));
    mn = fminf(fminf(smn[0][d], smn[1][d]), fminf(smn[2][d], smn[3][d]));

    float scale = (mx - mn) / 255.0f;
    if (scale <= 0.f) scale = 1.f;
    const float zero = rintf(-mn / scale);
    for (int t = dt; t < T_; t += 4) {
        float x = p[(size_t)t * D_];
        float q = fminf(fmaxf(rintf(x / scale) + zero, 0.f), 255.f);
        p[(size_t)t * D_] = scale * (q - zero);
    }
}

// ---------------------------------------------------------------------------
// Fused causal attention (flash-style, fp32). Block = (qtile of 64, bh).
// ---------------------------------------------------------------------------
static const int AP_ = 68;  // padded smem row stride (floats)

__global__ __launch_bounds__(256) void attn_fwd(
    const float* __restrict__ Q, const float* __restrict__ Kb,
    const float* __restrict__ Vb, float* __restrict__ ctx)
{
    extern __shared__ float sm[];
    float* Qs = sm;                 // [64][AP]
    float* Ks = sm + 64 * AP_;      // [64][AP], reused for P
    float* Vs = sm + 2 * 64 * AP_;  // [64][AP]

    const int bh = blockIdx.y;
    const int qt = blockIdx.x;
    const int q0 = qt * 64;
    const int tid = threadIdx.x;
    const int tx = tid & 15;
    const int ty = tid >> 4;
    const size_t base = (size_t)bh * T_ * D_;

#pragma unroll
    for (int it = 0; it < 16; it++) {
        int idx = it * 256 + tid;
        int r = idx >> 6, c = idx & 63;
        Qs[r * AP_ + c] = Q[base + (size_t)(q0 + r) * D_ + c];
    }

    float m_i[4], l_i[4], o[4][4];
#pragma unroll
    for (int i = 0; i < 4; i++) {
        m_i[i] = -1e30f;
        l_i[i] = 0.f;
#pragma unroll
        for (int x = 0; x < 4; x++) o[i][x] = 0.f;
    }

    for (int kt = 0; kt <= qt; kt++) {
        const int k0 = kt * 64;
        __syncthreads();
#pragma unroll
        for (int it = 0; it < 16; it++) {
            int idx = it * 256 + tid;
            int r = idx >> 6, c = idx & 63;
            Ks[r * AP_ + c] = Kb[base + (size_t)(k0 + r) * D_ + c];
            Vs[r * AP_ + c] = Vb[base + (size_t)(k0 + r) * D_ + c];
        }
        __syncthreads();

        float s_acc[4][4];
#pragma unroll
        for (int i = 0; i < 4; i++)
#pragma unroll
            for (int j = 0; j < 4; j++) s_acc[i][j] = 0.f;

#pragma unroll 16
        for (int dd = 0; dd < 64; dd++) {
            float a[4], b[4];
#pragma unroll
            for (int i = 0; i < 4; i++) a[i] = Qs[(ty + 16 * i) * AP_ + dd];
#pragma unroll
            for (int j = 0; j < 4; j++) b[j] = Ks[(tx + 16 * j) * AP_ + dd];
#pragma unroll
            for (int i = 0; i < 4; i++)
#pragma unroll
                for (int j = 0; j < 4; j++) s_acc[i][j] += a[i] * b[j];
        }

        if (kt == qt) {
#pragma unroll
            for (int i = 0; i < 4; i++)
#pragma unroll
                for (int j = 0; j < 4; j++)
                    if (tx + 16 * j > ty + 16 * i) s_acc[i][j] = -INFINITY;
        }

        float alpha[4];
#pragma unroll
        for (int i = 0; i < 4; i++) {
            float rm = fmaxf(fmaxf(s_acc[i][0], s_acc[i][1]),
                             fmaxf(s_acc[i][2], s_acc[i][3]));
#pragma unroll
            for (int off = 8; off > 0; off >>= 1)
                rm = fmaxf(rm, __shfl_xor_sync(0xffffffffu, rm, off));
            float mnew = fmaxf(m_i[i], rm);
            alpha[i] = __expf(m_i[i] - mnew);
            float rs = 0.f;
#pragma unroll
            for (int j = 0; j < 4; j++) {
                float pvi = __expf(s_acc[i][j] - mnew);
                s_acc[i][j] = pvi;
                rs += pvi;
            }
#pragma unroll
            for (int off = 8; off > 0; off >>= 1)
                rs += __shfl_xor_sync(0xffffffffu, rs, off);
            l_i[i] = l_i[i] * alpha[i] + rs;
            m_i[i] = mnew;
#pragma unroll
            for (int x = 0; x < 4; x++) o[i][x] *= alpha[i];
        }

        __syncthreads();
#pragma unroll
        for (int i = 0; i < 4; i++)
#pragma unroll
            for (int j = 0; j < 4; j++)
                Ks[(ty + 16 * i) * AP_ + (tx + 16 * j)] = s_acc[i][j];
        __syncthreads();

#pragma unroll 16
        for (int j0 = 0; j0 < 64; j0++) {
            const float4 bv = *(const float4*)(&Vs[j0 * AP_ + (tx << 2)]);
#pragma unroll
            for (int i = 0; i < 4; i++) {
                float a = Ks[(ty + 16 * i) * AP_ + j0];
                o[i][0] += a * bv.x;
                o[i][1] += a * bv.y;
                o[i][2] += a * bv.z;
                o[i][3] += a * bv.w;
            }
        }
    }

    const int b = bh >> 5;
    const int h = bh & 31;
#pragma unroll
    for (int i = 0; i < 4; i++) {
        const float inv = 1.0f / l_i[i];
        const int q = q0 + ty + 16 * i;
        float4 v;
        v.x = o[i][0] * inv; v.y = o[i][1] * inv;
        v.z = o[i][2] * inv; v.w = o[i][3] * inv;
        *(float4*)(&ctx[((size_t)(b * T_ + q)) * E_ + h * 64 + (tx << 2)]) = v;
    }
}

// ---------------------------------------------------------------------------
extern "C" void kernel_launch(void* const* d_in, const int* in_sizes, int n_in,
                              void* d_out, int out_size)
{
    (void)in_sizes; (void)n_in; (void)out_size;
    const float* hs = (const float*)d_in[0];
    const float* wq = (const float*)d_in[1];
    const float* bq = (const float*)d_in[2];
    const float* wk = (const float*)d_in[3];
    const float* bk = (const float*)d_in[4];
    const float* wv = (const float*)d_in[5];
    const float* bv = (const float*)d_in[6];
    const float* wo = (const float*)d_in[7];
    const float* bo = (const float*)d_in[8];
    float* out = (float*)d_out;

    float *q, *k, *v, *s, *ctx;
    cudaGetSymbolAddress((void**)&q, g_q);
    cudaGetSymbolAddress((void**)&k, g_k);
    cudaGetSymbolAddress((void**)&v, g_v);
    cudaGetSymbolAddress((void**)&s, g_s);
    cudaGetSymbolAddress((void**)&ctx, g_ctx);

    const int smem_attn = 3 * 64 * AP_ * (int)sizeof(float);  // 52224
    cudaFuncSetAttribute(attn_fwd, cudaFuncAttributeMaxDynamicSharedMemorySize,
                         smem_attn);
    cudaFuncSetAttribute(tc_gemm<0>, cudaFuncAttributeMaxDynamicSharedMemorySize,
                         GEMM_SMEM_);
    cudaFuncSetAttribute(tc_gemm<1>, cudaFuncAttributeMaxDynamicSharedMemorySize,
                         GEMM_SMEM_);

    dim3 gemmGrid(E_ / 128, BT_ / 128);  // (16, 32)

    // QKV projections (Q gets the d^-0.5 scaling folded into the epilogue)
    tc_gemm<1><<<gemmGrid, 256, GEMM_SMEM_>>>(hs, wq, bq, q, 0.125f);
    tc_gemm<1><<<gemmGrid, 256, GEMM_SMEM_>>>(hs, wk, bk, k, 1.0f);
    tc_gemm<1><<<gemmGrid, 256, GEMM_SMEM_>>>(hs, wv, bv, v, 1.0f);

    // SmoothK scale + fake quant K / Q / V
    smooth_absmax<<<BH_, 256>>>(k, s);
    row_quant<true><<<BH_ * T_ / 8, 256>>>(k, s);
    row_quant<false><<<BH_ * T_ / 8, 256>>>(q, nullptr);
    v_quant<<<BH_, 256>>>(v);

    // fused causal attention
    attn_fwd<<<dim3(T_ / 64, BH_), 256, smem_attn>>>(q, k, v, ctx);

    // output projection
    tc_gemm<0><<<gemmGrid, 256, GEMM_SMEM_>>>(ctx, wo, bo, out, 1.0f);
}

// round 4
// speedup vs baseline: 1.8179x; 1.3778x over previous
#include <cuda_runtime.h>
#include <cuda_fp16.h>
#include <math.h>
#include <stdint.h>

// Problem constants
static const int B_ = 4;
static const int T_ = 1024;
static const int E_ = 2048;
static const int H_ = 32;
static const int D_ = 64;
static const int BT_ = B_ * T_;      // 4096
static const int BH_ = B_ * H_;      // 128

// Scratch (device globals; no allocation allowed)
__device__ float g_q[BH_ * T_ * D_];   // [B,H,T,D]
__device__ float g_k[BH_ * T_ * D_];
__device__ float g_v[BH_ * T_ * D_];
__device__ float g_s[BH_ * D_];        // SmoothK per-channel scale
__device__ float g_ctx[BT_ * E_];      // attention output [B,T,E]

// ============================================================================
// fp16 two-term-split GEMM via mma.sync.m16n8k16 (baseline PTX).
// C = (A @ W^T + bias) * scale, with x = hi + lo/2048 (hi,lo fp16).
// main += Ah*Bh ; cross += Ah*Bl' + Al'*Bh ; C = main + cross/2048.
// CTA tile 128x128, K-chunk 32, 8 warps (2m x 4n), warp tile 64x32,
// 2-stage double-buffered smem with interleaved hi/lo fragment layout.
// MODE 0: C row-major [M,2048]. MODE 1: split-head out[b,h,t,d].
// ============================================================================
static const int GK_ = 2048;
static const int NCH_ = GK_ / 32;     // 64 chunks
static const int RSB_ = 192;          // bytes per row per chunk-stage (128+64 pad)
static const int OPBYTES_ = 128 * RSB_;          // 24576 per operand per stage
static const int GEMM_SMEM_ = 4 * OPBYTES_;      // A0,A1,B0,B1 = 98304

__device__ __forceinline__ void mma_f16(float* c, uint32_t a0, uint32_t a1,
                                        uint32_t a2, uint32_t a3,
                                        uint32_t b0, uint32_t b1) {
    asm volatile(
        "mma.sync.aligned.m16n8k16.row.col.f32.f16.f16.f32 "
        "{%0,%1,%2,%3}, {%4,%5,%6,%7}, {%8,%9}, {%0,%1,%2,%3};"
        : "+f"(c[0]), "+f"(c[1]), "+f"(c[2]), "+f"(c[3])
        : "r"(a0), "r"(a1), "r"(a2), "r"(a3), "r"(b0), "r"(b1));
}

// split two floats -> packed hi half2 and lo half2 (lo pre-scaled by 2048)
__device__ __forceinline__ void h2split(float x, float y, uint32_t& h,
                                        uint32_t& l) {
    __half2 hh = __floats2half2_rn(x, y);
    float2 hf = __half22float2(hh);
    __half2 ll = __floats2half2_rn((x - hf.x) * 2048.f, (y - hf.y) * 2048.f);
    h = *(uint32_t*)&hh;
    l = *(uint32_t*)&ll;
}

template <int MODE>
__global__ __launch_bounds__(256, 1) void tc_gemm(
    const float* __restrict__ A, const float* __restrict__ W,
    const float* __restrict__ bias, float* __restrict__ C, float scale)
{
    extern __shared__ char smem[];
    // layout: A stage0 @0, A stage1 @24576, B stage0 @49152, B stage1 @73728

    const int tid = threadIdx.x;
    const int wid = tid >> 5;
    const int lane = tid & 31;
    const int bm = blockIdx.y * 128;
    const int bn = blockIdx.x * 128;

    const int wm = (wid & 1) * 64;   // warp m offset
    const int wn = (wid >> 1) * 32;  // warp n offset
    const int gq = lane >> 2;        // 0..7
    const int tg = lane & 3;         // 0..3

    // ---- fill geometry ----
    // float4 g = tid + 256*j: row = tid>>3 + 32*j, k4 = tid&7 (same all j)
    const int row0 = tid >> 3;
    const int k4 = tid & 7;
    // pairs P0=2*k4 (x,y), P1=2*k4+1 (z,w); kstep = k4>>2
    const int ks_f = k4 >> 2;
    const int p0 = (2 * k4) & 7;
    const int p1 = p0 + 1;
    const int off_h0 = ks_f * 64 + (p0 & 3) * 16 + (p0 >> 2) * 4;
    const int off_h1 = ks_f * 64 + (p1 & 3) * 16 + (p1 >> 2) * 4;

    size_t offA[4], offB[4];
    int stsRow[4];
#pragma unroll
    for (int j = 0; j < 4; j++) {
        int r = row0 + 32 * j;
        stsRow[j] = r * RSB_;
        offA[j] = (size_t)(bm + r) * GK_ + k4 * 4;
        offB[j] = (size_t)(bn + r) * GK_ + k4 * 4;
    }

    float accM[4][4][4], accC[4][4][4];
#pragma unroll
    for (int mt = 0; mt < 4; mt++)
#pragma unroll
        for (int nt = 0; nt < 4; nt++)
#pragma unroll
            for (int x = 0; x < 4; x++) {
                accM[mt][nt][x] = 0.f;
                accC[mt][nt][x] = 0.f;
            }

    // ---- prologue: fill stage 0 with chunk 0 ----
    {
        char* sA = smem;
        char* sB = smem + 2 * OPBYTES_;
#pragma unroll
        for (int j = 0; j < 4; j++) {
            float4 va = *(const float4*)(A + offA[j]);
            float4 vb = *(const float4*)(W + offB[j]);
            uint32_t h0, l0, h1, l1;
            h2split(va.x, va.y, h0, l0);
            h2split(va.z, va.w, h1, l1);
            *(uint32_t*)(sA + stsRow[j] + off_h0) = h0;
            *(uint32_t*)(sA + stsRow[j] + off_h1) = h1;
            *(uint32_t*)(sA + stsRow[j] + off_h0 + 8) = l0;
            *(uint32_t*)(sA + stsRow[j] + off_h1 + 8) = l1;
            h2split(vb.x, vb.y, h0, l0);
            h2split(vb.z, vb.w, h1, l1);
            *(uint32_t*)(sB + stsRow[j] + off_h0) = h0;
            *(uint32_t*)(sB + stsRow[j] + off_h1) = h1;
            *(uint32_t*)(sB + stsRow[j] + off_h0 + 8) = l0;
            *(uint32_t*)(sB + stsRow[j] + off_h1 + 8) = l1;
        }
    }
    __syncthreads();

    for (int c = 0; c < NCH_; c++) {
        // prefetch chunk c+1 into registers
        float4 pa[4], pb[4];
        const bool pf = (c + 1 < NCH_);
        if (pf) {
            const int k0 = (c + 1) * 32;
#pragma unroll
            for (int j = 0; j < 4; j++) {
                pa[j] = *(const float4*)(A + offA[j] + k0);
                pb[j] = *(const float4*)(W + offB[j] + k0);
            }
        }

        // ---- MMA phase on stage c&1 ----
        const char* sA = smem + (c & 1) * OPBYTES_;
        const char* sB = smem + 2 * OPBYTES_ + (c & 1) * OPBYTES_;
#pragma unroll
        for (int ks = 0; ks < 2; ks++) {
            uint4 bf[4];
#pragma unroll
            for (int nt = 0; nt < 4; nt++)
                bf[nt] = *(const uint4*)(sB + (wn + nt * 8 + gq) * RSB_ +
                                         ks * 64 + tg * 16);
#pragma unroll
            for (int mt = 0; mt < 4; mt++) {
                const char* ra =
                    sA + (wm + mt * 16 + gq) * RSB_ + ks * 64 + tg * 16;
                uint4 t = *(const uint4*)(ra);
                uint4 u = *(const uint4*)(ra + 8 * RSB_);
#pragma unroll
                for (int nt = 0; nt < 4; nt++) {
                    mma_f16(accM[mt][nt], t.x, u.x, t.y, u.y, bf[nt].x, bf[nt].y);
                    mma_f16(accC[mt][nt], t.z, u.z, t.w, u.w, bf[nt].x, bf[nt].y);
                    mma_f16(accC[mt][nt], t.x, u.x, t.y, u.y, bf[nt].z, bf[nt].w);
                }
            }
        }

        // ---- STS chunk c+1 into stage (c+1)&1 ----
        if (pf) {
            char* dA = smem + ((c + 1) & 1) * OPBYTES_;
            char* dB = smem + 2 * OPBYTES_ + ((c + 1) & 1) * OPBYTES_;
#pragma unroll
            for (int j = 0; j < 4; j++) {
                uint32_t h0, l0, h1, l1;
                h2split(pa[j].x, pa[j].y, h0, l0);
                h2split(pa[j].z, pa[j].w, h1, l1);
                *(uint32_t*)(dA + stsRow[j] + off_h0) = h0;
                *(uint32_t*)(dA + stsRow[j] + off_h1) = h1;
                *(uint32_t*)(dA + stsRow[j] + off_h0 + 8) = l0;
                *(uint32_t*)(dA + stsRow[j] + off_h1 + 8) = l1;
                h2split(pb[j].x, pb[j].y, h0, l0);
                h2split(pb[j].z, pb[j].w, h1, l1);
                *(uint32_t*)(dB + stsRow[j] + off_h0) = h0;
                *(uint32_t*)(dB + stsRow[j] + off_h1) = h1;
                *(uint32_t*)(dB + stsRow[j] + off_h0 + 8) = l0;
                *(uint32_t*)(dB + stsRow[j] + off_h1 + 8) = l1;
            }
        }
        __syncthreads();
    }

    // ---- epilogue ----
    const float inv2048 = 1.0f / 2048.0f;
#pragma unroll
    for (int mt = 0; mt < 4; mt++) {
#pragma unroll
        for (int nt = 0; nt < 4; nt++) {
            const int n0 = bn + wn + nt * 8 + tg * 2;
            const float b0 = bias[n0], b1 = bias[n0 + 1];
#pragma unroll
            for (int half = 0; half < 2; half++) {
                const int m = bm + wm + mt * 16 + gq + half * 8;
                float2 v;
                v.x = (accM[mt][nt][half * 2 + 0] +
                       accC[mt][nt][half * 2 + 0] * inv2048 + b0) * scale;
                v.y = (accM[mt][nt][half * 2 + 1] +
                       accC[mt][nt][half * 2 + 1] * inv2048 + b1) * scale;
                if (MODE == 0) {
                    *(float2*)(C + (size_t)m * E_ + n0) = v;
                } else {
                    const int b = m >> 10, t = m & 1023;
                    const int h = n0 >> 6, d0 = n0 & 63;
                    *(float2*)(C + (((size_t)(b * H_ + h)) * T_ + t) * D_ + d0) = v;
                }
            }
        }
    }
}

// ---------------------------------------------------------------------------
// SmoothK per-channel abs-max over tokens
// ---------------------------------------------------------------------------
__global__ __launch_bounds__(256) void smooth_absmax(
    const float* __restrict__ Kin, float* __restrict__ S)
{
    const int bh = blockIdx.x;
    const int dt = threadIdx.x >> 6;
    const int d = threadIdx.x & 63;
    const float* p = Kin + (size_t)bh * T_ * D_ + d;
    float m = 0.f;
    for (int t = dt; t < T_; t += 4) m = fmaxf(m, fabsf(p[(size_t)t * D_]));
    __shared__ float sm[4][64];
    sm[dt][d] = m;
    __syncthreads();
    if (dt == 0) {
        float r = fmaxf(fmaxf(sm[0][d], sm[1][d]), fmaxf(sm[2][d], sm[3][d]));
        S[bh * 64 + d] = fmaxf(r, 1e-5f);
    }
}

// ---------------------------------------------------------------------------
// Per-row (over D=64) asymmetric fake quant
// ---------------------------------------------------------------------------
template <bool SMOOTH>
__global__ __launch_bounds__(256) void row_quant(
    float* __restrict__ X, const float* __restrict__ S)
{
    const int row = blockIdx.x * 8 + (threadIdx.x >> 5);
    const int lane = threadIdx.x & 31;
    float* p = X + (size_t)row * 64;

    float s0 = 1.f, s1 = 1.f;
    if (SMOOTH) {
        const int bh = row >> 10;
        s0 = S[bh * 64 + lane];
        s1 = S[bh * 64 + lane + 32];
    }
    float x0 = p[lane] / s0;
    float x1 = p[lane + 32] / s1;

    float mx = fmaxf(fmaxf(x0, x1), 0.f);
    float mn = fminf(fminf(x0, x1), 0.f);
#pragma unroll
    for (int o = 16; o > 0; o >>= 1) {
        mx = fmaxf(mx, __shfl_xor_sync(0xffffffffu, mx, o));
        mn = fminf(mn, __shfl_xor_sync(0xffffffffu, mn, o));
    }
    float scale = (mx - mn) / 255.0f;
    if (scale <= 0.f) scale = 1.f;
    const float zero = rintf(-mn / scale);
    float q0 = fminf(fmaxf(rintf(x0 / scale) + zero, 0.f), 255.f);
    float q1 = fminf(fmaxf(rintf(x1 / scale) + zero, 0.f), 255.f);
    p[lane]      = scale * (q0 - zero) * s0;
    p[lane + 32] = scale * (q1 - zero) * s1;
}

// ---------------------------------------------------------------------------
// V fake quant along the token axis
// ---------------------------------------------------------------------------
__global__ __launch_bounds__(256) void v_quant(float* __restrict__ V)
{
    const int bh = blockIdx.x;
    const int dt = threadIdx.x >> 6;
    const int d = threadIdx.x & 63;
    float* p = V + (size_t)bh * T_ * D_ + d;

    float mx = 0.f, mn = 0.f;
    for (int t = dt; t < T_; t += 4) {
        float x = p[(size_t)t * D_];
        mx = fmaxf(mx, x);
        mn = fminf(mn, x);
    }
    __shared__ float smx[4][64], smn[4][64];
    smx[dt][d] = mx; smn[dt][d] = mn;
    __syncthreads();
    mx = fmaxf(fmaxf(smx[0][d], smx[1][d]), fmaxf(smx[2][d], smx[3][d]));
    mn = fminf(fminf(smn[0][d], smn[1][d]), fminf(smn[2][d], smn[3][d]));

    float scale = (mx - mn) / 255.0f;
    if (scale <= 0.f) scale = 1.f;
    const float zero = rintf(-mn / scale);
    for (int t = dt; t < T_; t += 4) {
        float x = p[(size_t)t * D_];
        float q = fminf(fmaxf(rintf(x / scale) + zero, 0.f), 255.f);
        p[(size_t)t * D_] = scale * (q - zero);
    }
}

// ---------------------------------------------------------------------------
// Fused causal attention (flash-style, fp32). Block = (qtile of 64, bh).
// ---------------------------------------------------------------------------
static const int AP_ = 68;  // padded smem row stride (floats)

__global__ __launch_bounds__(256) void attn_fwd(
    const float* __restrict__ Q, const float* __restrict__ Kb,
    const float* __restrict__ Vb, float* __restrict__ ctx)
{
    extern __shared__ float sm[];
    float* Qs = sm;                 // [64][AP]
    float* Ks = sm + 64 * AP_;      // [64][AP], reused for P
    float* Vs = sm + 2 * 64 * AP_;  // [64][AP]

    const int bh = blockIdx.y;
    const int qt = blockIdx.x;
    const int q0 = qt * 64;
    const int tid = threadIdx.x;
    const int tx = tid & 15;
    const int ty = tid >> 4;
    const size_t base = (size_t)bh * T_ * D_;

#pragma unroll
    for (int it = 0; it < 16; it++) {
        int idx = it * 256 + tid;
        int r = idx >> 6, c = idx & 63;
        Qs[r * AP_ + c] = Q[base + (size_t)(q0 + r) * D_ + c];
    }

    float m_i[4], l_i[4], o[4][4];
#pragma unroll
    for (int i = 0; i < 4; i++) {
        m_i[i] = -1e30f;
        l_i[i] = 0.f;
#pragma unroll
        for (int x = 0; x < 4; x++) o[i][x] = 0.f;
    }

    for (int kt = 0; kt <= qt; kt++) {
        const int k0 = kt * 64;
        __syncthreads();
#pragma unroll
        for (int it = 0; it < 16; it++) {
            int idx = it * 256 + tid;
            int r = idx >> 6, c = idx & 63;
            Ks[r * AP_ + c] = Kb[base + (size_t)(k0 + r) * D_ + c];
            Vs[r * AP_ + c] = Vb[base + (size_t)(k0 + r) * D_ + c];
        }
        __syncthreads();

        float s_acc[4][4];
#pragma unroll
        for (int i = 0; i < 4; i++)
#pragma unroll
            for (int j = 0; j < 4; j++) s_acc[i][j] = 0.f;

#pragma unroll 16
        for (int dd = 0; dd < 64; dd++) {
            float a[4], b[4];
#pragma unroll
            for (int i = 0; i < 4; i++) a[i] = Qs[(ty + 16 * i) * AP_ + dd];
#pragma unroll
            for (int j = 0; j < 4; j++) b[j] = Ks[(tx + 16 * j) * AP_ + dd];
#pragma unroll
            for (int i = 0; i < 4; i++)
#pragma unroll
                for (int j = 0; j < 4; j++) s_acc[i][j] += a[i] * b[j];
        }

        if (kt == qt) {
#pragma unroll
            for (int i = 0; i < 4; i++)
#pragma unroll
                for (int j = 0; j < 4; j++)
                    if (tx + 16 * j > ty + 16 * i) s_acc[i][j] = -INFINITY;
        }

        float alpha[4];
#pragma unroll
        for (int i = 0; i < 4; i++) {
            float rm = fmaxf(fmaxf(s_acc[i][0], s_acc[i][1]),
                             fmaxf(s_acc[i][2], s_acc[i][3]));
#pragma unroll
            for (int off = 8; off > 0; off >>= 1)
                rm = fmaxf(rm, __shfl_xor_sync(0xffffffffu, rm, off));
            float mnew = fmaxf(m_i[i], rm);
            alpha[i] = __expf(m_i[i] - mnew);
            float rs = 0.f;
#pragma unroll
            for (int j = 0; j < 4; j++) {
                float pvi = __expf(s_acc[i][j] - mnew);
                s_acc[i][j] = pvi;
                rs += pvi;
            }
#pragma unroll
            for (int off = 8; off > 0; off >>= 1)
                rs += __shfl_xor_sync(0xffffffffu, rs, off);
            l_i[i] = l_i[i] * alpha[i] + rs;
            m_i[i] = mnew;
#pragma unroll
            for (int x = 0; x < 4; x++) o[i][x] *= alpha[i];
        }

        __syncthreads();
#pragma unroll
        for (int i = 0; i < 4; i++)
#pragma unroll
            for (int j = 0; j < 4; j++)
                Ks[(ty + 16 * i) * AP_ + (tx + 16 * j)] = s_acc[i][j];
        __syncthreads();

#pragma unroll 16
        for (int j0 = 0; j0 < 64; j0++) {
            const float4 bv = *(const float4*)(&Vs[j0 * AP_ + (tx << 2)]);
#pragma unroll
            for (int i = 0; i < 4; i++) {
                float a = Ks[(ty + 16 * i) * AP_ + j0];
                o[i][0] += a * bv.x;
                o[i][1] += a * bv.y;
                o[i][2] += a * bv.z;
                o[i][3] += a * bv.w;
            }
        }
    }

    const int b = bh >> 5;
    const int h = bh & 31;
#pragma unroll
    for (int i = 0; i < 4; i++) {
        const float inv = 1.0f / l_i[i];
        const int q = q0 + ty + 16 * i;
        float4 v;
        v.x = o[i][0] * inv; v.y = o[i][1] * inv;
        v.z = o[i][2] * inv; v.w = o[i][3] * inv;
        *(float4*)(&ctx[((size_t)(b * T_ + q)) * E_ + h * 64 + (tx << 2)]) = v;
    }
}

// ---------------------------------------------------------------------------
extern "C" void kernel_launch(void* const* d_in, const int* in_sizes, int n_in,
                              void* d_out, int out_size)
{
    (void)in_sizes; (void)n_in; (void)out_size;
    const float* hs = (const float*)d_in[0];
    const float* wq = (const float*)d_in[1];
    const float* bq = (const float*)d_in[2];
    const float* wk = (const float*)d_in[3];
    const float* bk = (const float*)d_in[4];
    const float* wv = (const float*)d_in[5];
    const float* bv = (const float*)d_in[6];
    const float* wo = (const float*)d_in[7];
    const float* bo = (const float*)d_in[8];
    float* out = (float*)d_out;

    float *q, *k, *v, *s, *ctx;
    cudaGetSymbolAddress((void**)&q, g_q);
    cudaGetSymbolAddress((void**)&k, g_k);
    cudaGetSymbolAddress((void**)&v, g_v);
    cudaGetSymbolAddress((void**)&s, g_s);
    cudaGetSymbolAddress((void**)&ctx, g_ctx);

    const int smem_attn = 3 * 64 * AP_ * (int)sizeof(float);  // 52224
    cudaFuncSetAttribute(attn_fwd, cudaFuncAttributeMaxDynamicSharedMemorySize,
                         smem_attn);
    cudaFuncSetAttribute(tc_gemm<0>, cudaFuncAttributeMaxDynamicSharedMemorySize,
                         GEMM_SMEM_);
    cudaFuncSetAttribute(tc_gemm<1>, cudaFuncAttributeMaxDynamicSharedMemorySize,
                         GEMM_SMEM_);

    dim3 gemmGrid(E_ / 128, BT_ / 128);  // (16, 32)

    // QKV projections (Q gets the d^-0.5 scaling folded into the epilogue)
    tc_gemm<1><<<gemmGrid, 256, GEMM_SMEM_>>>(hs, wq, bq, q, 0.125f);
    tc_gemm<1><<<gemmGrid, 256, GEMM_SMEM_>>>(hs, wk, bk, k, 1.0f);
    tc_gemm<1><<<gemmGrid, 256, GEMM_SMEM_>>>(hs, wv, bv, v, 1.0f);

    // SmoothK scale + fake quant K / Q / V
    smooth_absmax<<<BH_, 256>>>(k, s);
    row_quant<true><<<BH_ * T_ / 8, 256>>>(k, s);
    row_quant<false><<<BH_ * T_ / 8, 256>>>(q, nullptr);
    v_quant<<<BH_, 256>>>(v);

    // fused causal attention
    attn_fwd<<<dim3(T_ / 64, BH_), 256, smem_attn>>>(q, k, v, ctx);

    // output projection
    tc_gemm<0><<<gemmGrid, 256, GEMM_SMEM_>>>(ctx, wo, bo, out, 1.0f);
}

// round 6
// speedup vs baseline: 2.1257x; 1.1694x over previous
#include <cuda_runtime.h>
#include <cuda_fp16.h>
#include <math.h>
#include <stdint.h>

// Problem constants
static const int B_ = 4;
static const int T_ = 1024;
static const int E_ = 2048;
static const int H_ = 32;
static const int D_ = 64;
static const int BT_ = B_ * T_;      // 4096
static const int BH_ = B_ * H_;      // 128

// Scratch (device globals; no allocation allowed)
__device__ float g_q[BH_ * T_ * D_];   // [B,H,T,D]
__device__ float g_k[BH_ * T_ * D_];
__device__ float g_v[BH_ * T_ * D_];
__device__ float g_s[BH_ * D_];        // SmoothK per-channel scale
__device__ float g_ctx[BT_ * E_];      // attention output [B,T,E]

// ============================================================================
// common helpers
// ============================================================================
__device__ __forceinline__ void mma_f16(float* c, uint32_t a0, uint32_t a1,
                                        uint32_t a2, uint32_t a3,
                                        uint32_t b0, uint32_t b1) {
    asm volatile(
        "mma.sync.aligned.m16n8k16.row.col.f32.f16.f16.f32 "
        "{%0,%1,%2,%3}, {%4,%5,%6,%7}, {%8,%9}, {%0,%1,%2,%3};"
        : "+f"(c[0]), "+f"(c[1]), "+f"(c[2]), "+f"(c[3])
        : "r"(a0), "r"(a1), "r"(a2), "r"(a3), "r"(b0), "r"(b1));
}

// split two floats -> packed hi half2 and lo half2 (lo pre-scaled by 2048)
__device__ __forceinline__ void h2split(float x, float y, uint32_t& h,
                                        uint32_t& l) {
    __half2 hh = __floats2half2_rn(x, y);
    float2 hf = __half22float2(hh);
    __half2 ll = __floats2half2_rn((x - hf.x) * 2048.f, (y - hf.y) * 2048.f);
    h = *(uint32_t*)&hh;
    l = *(uint32_t*)&ll;
}

__device__ __forceinline__ void ldsm_x4_t(uint32_t& r0, uint32_t& r1,
                                          uint32_t& r2, uint32_t& r3,
                                          uint32_t addr) {
    asm volatile(
        "ldmatrix.sync.aligned.m8n8.x4.trans.shared.b16 {%0,%1,%2,%3}, [%4];"
        : "=r"(r0), "=r"(r1), "=r"(r2), "=r"(r3) : "r"(addr));
}

__device__ __forceinline__ uint32_t smem_u32(const void* p) {
    uint32_t a;
    asm("{ .reg .u64 t; cvta.to.shared.u64 t, %1; cvt.u32.u64 %0, t; }"
        : "=r"(a) : "l"(p));
    return a;
}

// ============================================================================
// fp16 two-term-split GEMM via mma.sync.m16n8k16 (as R4).
// ============================================================================
static const int GK_ = 2048;
static const int NCH_ = GK_ / 32;     // 64 chunks
static const int RSB_ = 192;          // bytes per row per chunk-stage
static const int OPBYTES_ = 128 * RSB_;          // 24576 per operand per stage
static const int GEMM_SMEM_ = 4 * OPBYTES_;      // 98304

template <int MODE>
__global__ __launch_bounds__(256, 1) void tc_gemm(
    const float* __restrict__ A, const float* __restrict__ W,
    const float* __restrict__ bias, float* __restrict__ C, float scale)
{
    extern __shared__ char smem[];

    const int tid = threadIdx.x;
    const int wid = tid >> 5;
    const int lane = tid & 31;
    const int bm = blockIdx.y * 128;
    const int bn = blockIdx.x * 128;

    const int wm = (wid & 1) * 64;
    const int wn = (wid >> 1) * 32;
    const int gq = lane >> 2;
    const int tg = lane & 3;

    const int row0 = tid >> 3;
    const int k4 = tid & 7;
    const int ks_f = k4 >> 2;
    const int p0 = (2 * k4) & 7;
    const int p1 = p0 + 1;
    const int off_h0 = ks_f * 64 + (p0 & 3) * 16 + (p0 >> 2) * 4;
    const int off_h1 = ks_f * 64 + (p1 & 3) * 16 + (p1 >> 2) * 4;

    size_t offA[4], offB[4];
    int stsRow[4];
#pragma unroll
    for (int j = 0; j < 4; j++) {
        int r = row0 + 32 * j;
        stsRow[j] = r * RSB_;
        offA[j] = (size_t)(bm + r) * GK_ + k4 * 4;
        offB[j] = (size_t)(bn + r) * GK_ + k4 * 4;
    }

    float accM[4][4][4], accC[4][4][4];
#pragma unroll
    for (int mt = 0; mt < 4; mt++)
#pragma unroll
        for (int nt = 0; nt < 4; nt++)
#pragma unroll
            for (int x = 0; x < 4; x++) {
                accM[mt][nt][x] = 0.f;
                accC[mt][nt][x] = 0.f;
            }

    {
        char* sA = smem;
        char* sB = smem + 2 * OPBYTES_;
#pragma unroll
        for (int j = 0; j < 4; j++) {
            float4 va = *(const float4*)(A + offA[j]);
            float4 vb = *(const float4*)(W + offB[j]);
            uint32_t h0, l0, h1, l1;
            h2split(va.x, va.y, h0, l0);
            h2split(va.z, va.w, h1, l1);
            *(uint32_t*)(sA + stsRow[j] + off_h0) = h0;
            *(uint32_t*)(sA + stsRow[j] + off_h1) = h1;
            *(uint32_t*)(sA + stsRow[j] + off_h0 + 8) = l0;
            *(uint32_t*)(sA + stsRow[j] + off_h1 + 8) = l1;
            h2split(vb.x, vb.y, h0, l0);
            h2split(vb.z, vb.w, h1, l1);
            *(uint32_t*)(sB + stsRow[j] + off_h0) = h0;
            *(uint32_t*)(sB + stsRow[j] + off_h1) = h1;
            *(uint32_t*)(sB + stsRow[j] + off_h0 + 8) = l0;
            *(uint32_t*)(sB + stsRow[j] + off_h1 + 8) = l1;
        }
    }
    __syncthreads();

    for (int c = 0; c < NCH_; c++) {
        float4 pa[4], pb[4];
        const bool pf = (c + 1 < NCH_);
        if (pf) {
            const int k0 = (c + 1) * 32;
#pragma unroll
            for (int j = 0; j < 4; j++) {
                pa[j] = *(const float4*)(A + offA[j] + k0);
                pb[j] = *(const float4*)(W + offB[j] + k0);
            }
        }

        const char* sA = smem + (c & 1) * OPBYTES_;
        const char* sB = smem + 2 * OPBYTES_ + (c & 1) * OPBYTES_;
#pragma unroll
        for (int ks = 0; ks < 2; ks++) {
            uint4 bf[4];
#pragma unroll
            for (int nt = 0; nt < 4; nt++)
                bf[nt] = *(const uint4*)(sB + (wn + nt * 8 + gq) * RSB_ +
                                         ks * 64 + tg * 16);
#pragma unroll
            for (int mt = 0; mt < 4; mt++) {
                const char* ra =
                    sA + (wm + mt * 16 + gq) * RSB_ + ks * 64 + tg * 16;
                uint4 t = *(const uint4*)(ra);
                uint4 u = *(const uint4*)(ra + 8 * RSB_);
#pragma unroll
                for (int nt = 0; nt < 4; nt++) {
                    mma_f16(accM[mt][nt], t.x, u.x, t.y, u.y, bf[nt].x, bf[nt].y);
                    mma_f16(accC[mt][nt], t.z, u.z, t.w, u.w, bf[nt].x, bf[nt].y);
                    mma_f16(accC[mt][nt], t.x, u.x, t.y, u.y, bf[nt].z, bf[nt].w);
                }
            }
        }

        if (pf) {
            char* dA = smem + ((c + 1) & 1) * OPBYTES_;
            char* dB = smem + 2 * OPBYTES_ + ((c + 1) & 1) * OPBYTES_;
#pragma unroll
            for (int j = 0; j < 4; j++) {
                uint32_t h0, l0, h1, l1;
                h2split(pa[j].x, pa[j].y, h0, l0);
                h2split(pa[j].z, pa[j].w, h1, l1);
                *(uint32_t*)(dA + stsRow[j] + off_h0) = h0;
                *(uint32_t*)(dA + stsRow[j] + off_h1) = h1;
                *(uint32_t*)(dA + stsRow[j] + off_h0 + 8) = l0;
                *(uint32_t*)(dA + stsRow[j] + off_h1 + 8) = l1;
                h2split(pb[j].x, pb[j].y, h0, l0);
                h2split(pb[j].z, pb[j].w, h1, l1);
                *(uint32_t*)(dB + stsRow[j] + off_h0) = h0;
                *(uint32_t*)(dB + stsRow[j] + off_h1) = h1;
                *(uint32_t*)(dB + stsRow[j] + off_h0 + 8) = l0;
                *(uint32_t*)(dB + stsRow[j] + off_h1 + 8) = l1;
            }
        }
        __syncthreads();
    }

    const float inv2048 = 1.0f / 2048.0f;
#pragma unroll
    for (int mt = 0; mt < 4; mt++) {
#pragma unroll
        for (int nt = 0; nt < 4; nt++) {
            const int n0 = bn + wn + nt * 8 + tg * 2;
            const float b0 = bias[n0], b1 = bias[n0 + 1];
#pragma unroll
            for (int half = 0; half < 2; half++) {
                const int m = bm + wm + mt * 16 + gq + half * 8;
                float2 v;
                v.x = (accM[mt][nt][half * 2 + 0] +
                       accC[mt][nt][half * 2 + 0] * inv2048 + b0) * scale;
                v.y = (accM[mt][nt][half * 2 + 1] +
                       accC[mt][nt][half * 2 + 1] * inv2048 + b1) * scale;
                if (MODE == 0) {
                    *(float2*)(C + (size_t)m * E_ + n0) = v;
                } else {
                    const int b = m >> 10, t = m & 1023;
                    const int h = n0 >> 6, d0 = n0 & 63;
                    *(float2*)(C + (((size_t)(b * H_ + h)) * T_ + t) * D_ + d0) = v;
                }
            }
        }
    }
}

// ---------------------------------------------------------------------------
// SmoothK per-channel abs-max over tokens
// ---------------------------------------------------------------------------
__global__ __launch_bounds__(256) void smooth_absmax(
    const float* __restrict__ Kin, float* __restrict__ S)
{
    const int bh = blockIdx.x;
    const int dt = threadIdx.x >> 6;
    const int d = threadIdx.x & 63;
    const float* p = Kin + (size_t)bh * T_ * D_ + d;
    float m = 0.f;
    for (int t = dt; t < T_; t += 4) m = fmaxf(m, fabsf(p[(size_t)t * D_]));
    __shared__ float sm[4][64];
    sm[dt][d] = m;
    __syncthreads();
    if (dt == 0) {
        float r = fmaxf(fmaxf(sm[0][d], sm[1][d]), fmaxf(sm[2][d], sm[3][d]));
        S[bh * 64 + d] = fmaxf(r, 1e-5f);
    }
}

// ---------------------------------------------------------------------------
// Per-row (over D=64) asymmetric fake quant
// ---------------------------------------------------------------------------
template <bool SMOOTH>
__global__ __launch_bounds__(256) void row_quant(
    float* __restrict__ X, const float* __restrict__ S)
{
    const int row = blockIdx.x * 8 + (threadIdx.x >> 5);
    const int lane = threadIdx.x & 31;
    float* p = X + (size_t)row * 64;

    float s0 = 1.f, s1 = 1.f;
    if (SMOOTH) {
        const int bh = row >> 10;
        s0 = S[bh * 64 + lane];
        s1 = S[bh * 64 + lane + 32];
    }
    float x0 = p[lane] / s0;
    float x1 = p[lane + 32] / s1;

    float mx = fmaxf(fmaxf(x0, x1), 0.f);
    float mn = fminf(fminf(x0, x1), 0.f);
#pragma unroll
    for (int o = 16; o > 0; o >>= 1) {
        mx = fmaxf(mx, __shfl_xor_sync(0xffffffffu, mx, o));
        mn = fminf(mn, __shfl_xor_sync(0xffffffffu, mn, o));
    }
    float scale = (mx - mn) / 255.0f;
    if (scale <= 0.f) scale = 1.f;
    const float zero = rintf(-mn / scale);
    float q0 = fminf(fmaxf(rintf(x0 / scale) + zero, 0.f), 255.f);
    float q1 = fminf(fmaxf(rintf(x1 / scale) + zero, 0.f), 255.f);
    p[lane]      = scale * (q0 - zero) * s0;
    p[lane + 32] = scale * (q1 - zero) * s1;
}

// ---------------------------------------------------------------------------
// V fake quant along the token axis
// ---------------------------------------------------------------------------
__global__ __launch_bounds__(256) void v_quant(float* __restrict__ V)
{
    const int bh = blockIdx.x;
    const int dt = threadIdx.x >> 6;
    const int d = threadIdx.x & 63;
    float* p = V + (size_t)bh * T_ * D_ + d;

    float mx = 0.f, mn = 0.f;
    for (int t = dt; t < T_; t += 4) {
        float x = p[(size_t)t * D_];
        mx = fmaxf(mx, x);
        mn = fminf(mn, x);
    }
    __shared__ float smx[4][64], smn[4][64];
    smx[dt][d] = mx; smn[dt][d] = mn;
    __syncthreads();
    mx = fmaxf(fmaxf(smx[0][d], smx[1][d]), fmaxf(smx[2][d], smx[3][d]));
    mn = fminf(fminf(smn[0][d], smn[1][d]), fminf(smn[2][d], smn[3][d]));

    float scale = (mx - mn) / 255.0f;
    if (scale <= 0.f) scale = 1.f;
    const float zero = rintf(-mn / scale);
    for (int t = dt; t < T_; t += 4) {
        float x = p[(size_t)t * D_];
        float q = fminf(fmaxf(rintf(x / scale) + zero, 0.f), 255.f);
        p[(size_t)t * D_] = scale * (q - zero);
    }
}

// ============================================================================
// Tensor-core flash attention (fp16 two-term split, 3-pass).
// Block = (qtile of 128 rows, bh). 8 warps x 16 q-rows (FA2 layout).
// K-tiles of 64 tokens, double-buffered. Q/K in interleaved hi/lo layout
// (stride 320B); V as fp16 hi/lo [tok][d] tiles read via ldmatrix.x4.trans.
// ============================================================================
static const int QKS_ = 320;                 // Q/K row stride (bytes)
static const int VS_ = 144;                  // V row stride (bytes)
static const int SM_Q_ = 0;                  // 128*320 = 40960
static const int SM_K_ = 40960;              // 2 stages x 64*320 = 40960
static const int SM_V_ = 81920;              // 2 stages x (Vh 9216 + Vl 9216)
static const int ATTN_SMEM_ = 81920 + 2 * 18432;  // 118784

__global__ __launch_bounds__(256, 1) void attn_mma(
    const float* __restrict__ Q, const float* __restrict__ Kb,
    const float* __restrict__ Vb, float* __restrict__ ctx)
{
    extern __shared__ char smem[];
    const uint32_t sb = smem_u32(smem);

    const int bh = blockIdx.y;
    const int qt = 7 - blockIdx.x;          // big tiles first
    const int tid = threadIdx.x;
    const int wid = tid >> 5;
    const int lane = tid & 31;
    const int gq = lane >> 2;
    const int tg = lane & 3;
    const size_t base = (size_t)bh * T_ * D_;

    // fill geometry (float4 over [rows][16 f4])
    const int frow = tid >> 4;          // 0..15 (+16*j)
    const int f4 = tid & 15;
    const int ks_f = f4 >> 2;
    const int p0 = (2 * f4) & 7;
    const int p1 = p0 + 1;
    const int off_h0 = ks_f * 64 + (p0 & 3) * 16 + (p0 >> 2) * 4;
    const int off_h1 = ks_f * 64 + (p1 & 3) * 16 + (p1 >> 2) * 4;

    // ---- fill Q tile (128 rows) ----
#pragma unroll
    for (int j = 0; j < 8; j++) {
        const int r = frow + 16 * j;
        float4 v = *(const float4*)(Q + base + (size_t)(qt * 128 + r) * D_ + f4 * 4);
        uint32_t h0, l0, h1, l1;
        h2split(v.x, v.y, h0, l0);
        h2split(v.z, v.w, h1, l1);
        char* dst = smem + SM_Q_ + r * QKS_;
        *(uint32_t*)(dst + off_h0) = h0;
        *(uint32_t*)(dst + off_h1) = h1;
        *(uint32_t*)(dst + off_h0 + 8) = l0;
        *(uint32_t*)(dst + off_h1 + 8) = l1;
    }

    // ---- fill K/V ktile 0, stage 0 ----
    {
#pragma unroll
        for (int j = 0; j < 4; j++) {
            const int r = frow + 16 * j;   // token 0..63
            float4 kv = *(const float4*)(Kb + base + (size_t)r * D_ + f4 * 4);
            uint32_t h0, l0, h1, l1;
            h2split(kv.x, kv.y, h0, l0);
            h2split(kv.z, kv.w, h1, l1);
            char* dst = smem + SM_K_ + r * QKS_;
            *(uint32_t*)(dst + off_h0) = h0;
            *(uint32_t*)(dst + off_h1) = h1;
            *(uint32_t*)(dst + off_h0 + 8) = l0;
            *(uint32_t*)(dst + off_h1 + 8) = l1;

            float4 vv = *(const float4*)(Vb + base + (size_t)r * D_ + f4 * 4);
            h2split(vv.x, vv.y, h0, l0);
            h2split(vv.z, vv.w, h1, l1);
            char* vh = smem + SM_V_ + r * VS_ + f4 * 8;
            *(uint2*)(vh) = make_uint2(h0, h1);
            *(uint2*)(vh + 9216) = make_uint2(l0, l1);
        }
    }
    __syncthreads();

    float O[8][4];
#pragma unroll
    for (int nt = 0; nt < 8; nt++)
#pragma unroll
        for (int x = 0; x < 4; x++) O[nt][x] = 0.f;
    float m0 = -1e30f, m1 = -1e30f, l0s = 0.f, l1s = 0.f;

    const int r0g = qt * 128 + wid * 16 + gq;   // global q row (frag half 0)
    const int r1g = r0g + 8;
    const int nkt = 2 * (qt + 1);
    const float inv2048 = 1.0f / 2048.0f;
    const int vrow_off = (lane & 15) * VS_ + (lane >> 4) * 16;

    for (int kt = 0; kt < nkt; kt++) {
        const int stage = kt & 1;
        const uint32_t kbase = sb + SM_K_ + stage * 20480;
        const uint32_t vhbase = sb + SM_V_ + stage * 18432;

        // prefetch next ktile into registers
        float4 pk[4], pv[4];
        const bool pf = (kt + 1 < nkt);
        if (pf) {
            const size_t tok0 = (size_t)(kt + 1) * 64;
#pragma unroll
            for (int j = 0; j < 4; j++) {
                const size_t r = tok0 + frow + 16 * j;
                pk[j] = *(const float4*)(Kb + base + r * D_ + f4 * 4);
                pv[j] = *(const float4*)(Vb + base + r * D_ + f4 * 4);
            }
        }

        // ---- S = Q @ K^T (3-pass) ----
        float sm_[8][4], sc_[8][4];
#pragma unroll
        for (int nt = 0; nt < 8; nt++)
#pragma unroll
            for (int x = 0; x < 4; x++) { sm_[nt][x] = 0.f; sc_[nt][x] = 0.f; }

        const uint32_t qbase = sb + SM_Q_ + (wid * 16 + gq) * QKS_;
#pragma unroll
        for (int ks = 0; ks < 4; ks++) {
            uint4 tq, uq;
            asm volatile("ld.shared.v4.b32 {%0,%1,%2,%3}, [%4];"
                         : "=r"(tq.x), "=r"(tq.y), "=r"(tq.z), "=r"(tq.w)
                         : "r"(qbase + ks * 64 + tg * 16));
            asm volatile("ld.shared.v4.b32 {%0,%1,%2,%3}, [%4];"
                         : "=r"(uq.x), "=r"(uq.y), "=r"(uq.z), "=r"(uq.w)
                         : "r"(qbase + 8 * QKS_ + ks * 64 + tg * 16));
#pragma unroll
            for (int nt = 0; nt < 8; nt++) {
                uint4 bk;
                asm volatile("ld.shared.v4.b32 {%0,%1,%2,%3}, [%4];"
                             : "=r"(bk.x), "=r"(bk.y), "=r"(bk.z), "=r"(bk.w)
                             : "r"(kbase + (nt * 8 + gq) * QKS_ + ks * 64 + tg * 16));
                mma_f16(sm_[nt], tq.x, uq.x, tq.y, uq.y, bk.x, bk.y);
                mma_f16(sc_[nt], tq.z, uq.z, tq.w, uq.w, bk.x, bk.y);
                mma_f16(sc_[nt], tq.x, uq.x, tq.y, uq.y, bk.z, bk.w);
            }
        }

        // fold cross term; causal mask (only possible on last two ktiles)
        float s[8][4];
        const bool maskit = (kt >= 2 * qt);
#pragma unroll
        for (int nt = 0; nt < 8; nt++)
#pragma unroll
            for (int x = 0; x < 4; x++) {
                float v = sm_[nt][x] + sc_[nt][x] * inv2048;
                if (maskit) {
                    const int col = kt * 64 + nt * 8 + tg * 2 + (x & 1);
                    const int row = (x < 2) ? r0g : r1g;
                    if (col > row) v = -INFINITY;
                }
                s[nt][x] = v;
            }

        // online softmax (rows r0g, r1g; replicated across tg quad)
        float rm0 = -1e30f, rm1 = -1e30f;
#pragma unroll
        for (int nt = 0; nt < 8; nt++) {
            rm0 = fmaxf(rm0, fmaxf(s[nt][0], s[nt][1]));
            rm1 = fmaxf(rm1, fmaxf(s[nt][2], s[nt][3]));
        }
        rm0 = fmaxf(rm0, __shfl_xor_sync(0xffffffffu, rm0, 1));
        rm0 = fmaxf(rm0, __shfl_xor_sync(0xffffffffu, rm0, 2));
        rm1 = fmaxf(rm1, __shfl_xor_sync(0xffffffffu, rm1, 1));
        rm1 = fmaxf(rm1, __shfl_xor_sync(0xffffffffu, rm1, 2));

        const float mn0 = fmaxf(m0, rm0);
        const float mn1 = fmaxf(m1, rm1);
        const float a0 = __expf(m0 - mn0);
        const float a1 = __expf(m1 - mn1);
        float rs0 = 0.f, rs1 = 0.f;
#pragma unroll
        for (int nt = 0; nt < 8; nt++) {
            s[nt][0] = __expf(s[nt][0] - mn0);
            s[nt][1] = __expf(s[nt][1] - mn0);
            s[nt][2] = __expf(s[nt][2] - mn1);
            s[nt][3] = __expf(s[nt][3] - mn1);
            rs0 += s[nt][0] + s[nt][1];
            rs1 += s[nt][2] + s[nt][3];
        }
        rs0 += __shfl_xor_sync(0xffffffffu, rs0, 1);
        rs0 += __shfl_xor_sync(0xffffffffu, rs0, 2);
        rs1 += __shfl_xor_sync(0xffffffffu, rs1, 1);
        rs1 += __shfl_xor_sync(0xffffffffu, rs1, 2);
        l0s = l0s * a0 + rs0;
        l1s = l1s * a1 + rs1;
        m0 = mn0;
        m1 = mn1;
#pragma unroll
        for (int nt = 0; nt < 8; nt++) {
            O[nt][0] *= a0; O[nt][1] *= a0;
            O[nt][2] *= a1; O[nt][3] *= a1;
        }

        // convert P -> A fragments (hi/lo)
        uint32_t ph[4][4], pl[4][4];
#pragma unroll
        for (int j = 0; j < 4; j++) {
            h2split(s[2 * j][0], s[2 * j][1], ph[j][0], pl[j][0]);
            h2split(s[2 * j][2], s[2 * j][3], ph[j][1], pl[j][1]);
            h2split(s[2 * j + 1][0], s[2 * j + 1][1], ph[j][2], pl[j][2]);
            h2split(s[2 * j + 1][2], s[2 * j + 1][3], ph[j][3], pl[j][3]);
        }

        // ---- O += P @ V (3-pass) ----
        // n-pair np covers d = np*16 .. np*16+15 (byte offset np*32);
        // accumulators O[np*2], O[np*2+1].
        float Oc[8][4];
#pragma unroll
        for (int nt = 0; nt < 8; nt++)
#pragma unroll
            for (int x = 0; x < 4; x++) Oc[nt][x] = 0.f;

#pragma unroll
        for (int j = 0; j < 4; j++) {        // kstep: tokens 16j..16j+15
            const uint32_t krow = vhbase + j * 16 * VS_ + vrow_off;
#pragma unroll
            for (int np = 0; np < 4; np++) {
                uint32_t vh0, vh1, vh2, vh3, vl0, vl1, vl2, vl3;
                ldsm_x4_t(vh0, vh1, vh2, vh3, krow + np * 32);
                ldsm_x4_t(vl0, vl1, vl2, vl3, krow + 9216 + np * 32);
                const int nt = np * 2;
                mma_f16(O[nt], ph[j][0], ph[j][1], ph[j][2], ph[j][3], vh0, vh1);
                mma_f16(Oc[nt], pl[j][0], pl[j][1], pl[j][2], pl[j][3], vh0, vh1);
                mma_f16(Oc[nt], ph[j][0], ph[j][1], ph[j][2], ph[j][3], vl0, vl1);
                mma_f16(O[nt + 1], ph[j][0], ph[j][1], ph[j][2], ph[j][3], vh2, vh3);
                mma_f16(Oc[nt + 1], pl[j][0], pl[j][1], pl[j][2], pl[j][3], vh2, vh3);
                mma_f16(Oc[nt + 1], ph[j][0], ph[j][1], ph[j][2], ph[j][3], vl2, vl3);
            }
        }

#pragma unroll
        for (int nt = 0; nt < 8; nt++)
#pragma unroll
            for (int x = 0; x < 4; x++) O[nt][x] += Oc[nt][x] * inv2048;

        // ---- store prefetched ktile into other stage ----
        if (pf) {
            const int ns = stage ^ 1;
            char* kdst = smem + SM_K_ + ns * 20480;
            char* vdst = smem + SM_V_ + ns * 18432;
#pragma unroll
            for (int j = 0; j < 4; j++) {
                const int r = frow + 16 * j;
                uint32_t h0, l0, h1, l1;
                h2split(pk[j].x, pk[j].y, h0, l0);
                h2split(pk[j].z, pk[j].w, h1, l1);
                char* dst = kdst + r * QKS_;
                *(uint32_t*)(dst + off_h0) = h0;
                *(uint32_t*)(dst + off_h1) = h1;
                *(uint32_t*)(dst + off_h0 + 8) = l0;
                *(uint32_t*)(dst + off_h1 + 8) = l1;
                h2split(pv[j].x, pv[j].y, h0, l0);
                h2split(pv[j].z, pv[j].w, h1, l1);
                char* vh = vdst + r * VS_ + f4 * 8;
                *(uint2*)(vh) = make_uint2(h0, h1);
                *(uint2*)(vh + 9216) = make_uint2(l0, l1);
            }
        }
        __syncthreads();
    }

    // ---- epilogue: normalize, write ctx[b, t, h*64+d] ----
    const int b = bh >> 5;
    const int h = bh & 31;
    const float i0 = 1.0f / l0s;
    const float i1 = 1.0f / l1s;
#pragma unroll
    for (int nt = 0; nt < 8; nt++) {
        const int d0 = nt * 8 + tg * 2;
        float2 v0, v1;
        v0.x = O[nt][0] * i0; v0.y = O[nt][1] * i0;
        v1.x = O[nt][2] * i1; v1.y = O[nt][3] * i1;
        *(float2*)(&ctx[((size_t)(b * T_ + r0g)) * E_ + h * 64 + d0]) = v0;
        *(float2*)(&ctx[((size_t)(b * T_ + r1g)) * E_ + h * 64 + d0]) = v1;
    }
}

// ---------------------------------------------------------------------------
extern "C" void kernel_launch(void* const* d_in, const int* in_sizes, int n_in,
                              void* d_out, int out_size)
{
    (void)in_sizes; (void)n_in; (void)out_size;
    const float* hs = (const float*)d_in[0];
    const float* wq = (const float*)d_in[1];
    const float* bq = (const float*)d_in[2];
    const float* wk = (const float*)d_in[3];
    const float* bk = (const float*)d_in[4];
    const float* wv = (const float*)d_in[5];
    const float* bv = (const float*)d_in[6];
    const float* wo = (const float*)d_in[7];
    const float* bo = (const float*)d_in[8];
    float* out = (float*)d_out;

    float *q, *k, *v, *s, *ctx;
    cudaGetSymbolAddress((void**)&q, g_q);
    cudaGetSymbolAddress((void**)&k, g_k);
    cudaGetSymbolAddress((void**)&v, g_v);
    cudaGetSymbolAddress((void**)&s, g_s);
    cudaGetSymbolAddress((void**)&ctx, g_ctx);

    cudaFuncSetAttribute(tc_gemm<0>, cudaFuncAttributeMaxDynamicSharedMemorySize,
                         GEMM_SMEM_);
    cudaFuncSetAttribute(tc_gemm<1>, cudaFuncAttributeMaxDynamicSharedMemorySize,
                         GEMM_SMEM_);
    cudaFuncSetAttribute(attn_mma, cudaFuncAttributeMaxDynamicSharedMemorySize,
                         ATTN_SMEM_);

    dim3 gemmGrid(E_ / 128, BT_ / 128);  // (16, 32)

    // QKV projections (Q gets the d^-0.5 scaling folded into the epilogue)
    tc_gemm<1><<<gemmGrid, 256, GEMM_SMEM_>>>(hs, wq, bq, q, 0.125f);
    tc_gemm<1><<<gemmGrid, 256, GEMM_SMEM_>>>(hs, wk, bk, k, 1.0f);
    tc_gemm<1><<<gemmGrid, 256, GEMM_SMEM_>>>(hs, wv, bv, v, 1.0f);

    // SmoothK scale + fake quant K / Q / V
    smooth_absmax<<<BH_, 256>>>(k, s);
    row_quant<true><<<BH_ * T_ / 8, 256>>>(k, s);
    row_quant<false><<<BH_ * T_ / 8, 256>>>(q, nullptr);
    v_quant<<<BH_, 256>>>(v);

    // fused tensor-core causal attention
    attn_mma<<<dim3(8, BH_), 256, ATTN_SMEM_>>>(q, k, v, ctx);

    // output projection
    tc_gemm<0><<<gemmGrid, 256, GEMM_SMEM_>>>(ctx, wo, bo, out, 1.0f);
}